// round 17
// baseline (speedup 1.0000x reference)
#include <cuda_runtime.h>
#include <cuda_fp16.h>
#include <cstdint>
#include <cstddef>

#define NB 2
#define NT 2048
#define ND 1024
#define NH 16
#define NLAY 2
#define NE 8
#define NV 32000
#define NN (NB*NT)
#define NCAP 1024
#define NFF 4096
#define NPART (NV/128)

// ---------------- device scratch ----------------
__device__ float  g_x   [(size_t)NN*ND];
__device__ __half g_ln16[(size_t)NN*ND];
__device__ __half g_qkv16[(size_t)NN*3*ND];
__device__ __half g_attn16[(size_t)NN*ND];
__device__ float  g_route[NN*NE];
__device__ float  g_noise[NN*NE];
__device__ float  g_gate [NN*NE];
__device__ unsigned char g_mask[NN];
__device__ int    g_sel [NE*NCAP];
__device__ int    g_slot[NE*NN];
__device__ int    g_cnt [NE];
__device__ __half g_h116[(size_t)NE*NCAP*NFF];
__device__ __half g_eo16[(size_t)NE*NCAP*ND];
__device__ float2 g_part[(size_t)NN*NPART];
__device__ float  g_tlog[NN];
__device__ float  g_nll [NN];
__device__ float  g_vld [NN];
// fp16 weight copies (ORIGINAL [K,N] layout — no transpose)
__device__ __half g_wqkv16[(size_t)NLAY*ND*3*ND];
__device__ __half g_wout16[(size_t)NLAY*ND*ND];
__device__ __half g_we116 [(size_t)NLAY*NE*ND*NFF];
__device__ __half g_we216 [(size_t)NLAY*NE*NFF*ND];
__device__ __half g_tok16 [(size_t)NV*ND];

// ---------------- threefry2x32 (matches JAX) ----------------
__host__ __device__ __forceinline__ void threefry(unsigned k0, unsigned k1,
                                                  unsigned x0, unsigned x1,
                                                  unsigned& o0, unsigned& o1) {
    unsigned ks2 = k0 ^ k1 ^ 0x1BD11BDAu;
    x0 += k0; x1 += k1;
#define TFR(r) { x0 += x1; x1 = (x1 << (r)) | (x1 >> (32 - (r))); x1 ^= x0; }
    TFR(13) TFR(15) TFR(26) TFR(6)  x0 += k1;  x1 += ks2 + 1u;
    TFR(17) TFR(29) TFR(16) TFR(24) x0 += ks2; x1 += k0 + 2u;
    TFR(13) TFR(15) TFR(26) TFR(6)  x0 += k0;  x1 += k1 + 3u;
    TFR(17) TFR(29) TFR(16) TFR(24) x0 += k1;  x1 += ks2 + 4u;
    TFR(13) TFR(15) TFR(26) TFR(6)  x0 += ks2; x1 += k0 + 5u;
#undef TFR
    o0 = x0; o1 = x1;
}

__device__ __forceinline__ float xla_erfinv(float x) {
    float w = -log1pf(-x * x);
    float p;
    if (w < 5.f) {
        w -= 2.5f;
        p = 2.81022636e-08f;
        p = fmaf(p, w, 3.43273939e-07f);
        p = fmaf(p, w, -3.5233877e-06f);
        p = fmaf(p, w, -4.39150654e-06f);
        p = fmaf(p, w, 0.00021858087f);
        p = fmaf(p, w, -0.00125372503f);
        p = fmaf(p, w, -0.00417768164f);
        p = fmaf(p, w, 0.246640727f);
        p = fmaf(p, w, 1.50140941f);
    } else {
        w = sqrtf(w) - 3.f;
        p = -0.000200214257f;
        p = fmaf(p, w, 0.000100950558f);
        p = fmaf(p, w, 0.00134934322f);
        p = fmaf(p, w, -0.00367342844f);
        p = fmaf(p, w, 0.00573950773f);
        p = fmaf(p, w, -0.0076224613f);
        p = fmaf(p, w, 0.00943887047f);
        p = fmaf(p, w, 1.00167406f);
        p = fmaf(p, w, 2.83297682f);
    }
    return p * x;
}

__device__ __forceinline__ float bits_to_normal(unsigned bits) {
    float f = __uint_as_float((bits >> 9) | 0x3F800000u) - 1.0f;
    const float lo = -0.99999994f;
    float u = fmaf(f, 2.0f, lo);
    u = fmaxf(u, lo);
    return 1.41421356237f * xla_erfinv(u);
}

// ---------------- mma / ldmatrix / cp.async helpers ----------------
__device__ __forceinline__ void mma_f16(float* c, const unsigned* a, const unsigned* b) {
    asm volatile("mma.sync.aligned.m16n8k16.row.col.f32.f16.f16.f32 "
        "{%0,%1,%2,%3}, {%4,%5,%6,%7}, {%8,%9}, {%0,%1,%2,%3};"
        : "+f"(c[0]), "+f"(c[1]), "+f"(c[2]), "+f"(c[3])
        : "r"(a[0]), "r"(a[1]), "r"(a[2]), "r"(a[3]), "r"(b[0]), "r"(b[1]));
}
// fp16-accumulator variant (vocab only)
__device__ __forceinline__ void mma_f16h(unsigned* c, const unsigned* a, const unsigned* b) {
    asm volatile("mma.sync.aligned.m16n8k16.row.col.f16.f16.f16.f16 "
        "{%0,%1}, {%2,%3,%4,%5}, {%6,%7}, {%0,%1};"
        : "+r"(c[0]), "+r"(c[1])
        : "r"(a[0]), "r"(a[1]), "r"(a[2]), "r"(a[3]), "r"(b[0]), "r"(b[1]));
}
__device__ __forceinline__ void ldsm4(unsigned& d0, unsigned& d1, unsigned& d2, unsigned& d3,
                                      uint32_t addr) {
    asm volatile("ldmatrix.sync.aligned.m8n8.x4.shared.b16 {%0,%1,%2,%3}, [%4];"
        : "=r"(d0), "=r"(d1), "=r"(d2), "=r"(d3) : "r"(addr));
}
__device__ __forceinline__ void ldsm4t(unsigned& d0, unsigned& d1, unsigned& d2, unsigned& d3,
                                       uint32_t addr) {
    asm volatile("ldmatrix.sync.aligned.m8n8.x4.trans.shared.b16 {%0,%1,%2,%3}, [%4];"
        : "=r"(d0), "=r"(d1), "=r"(d2), "=r"(d3) : "r"(addr));
}
__device__ __forceinline__ uint32_t smem_u32(const void* p) {
    uint32_t a;
    asm("{ .reg .u64 t; cvta.to.shared.u64 t, %1; cvt.u32.u64 %0, t; }" : "=r"(a) : "l"(p));
    return a;
}
__device__ __forceinline__ void cpa16(uint32_t dst, const void* src) {
    asm volatile("cp.async.ca.shared.global [%0], [%1], 16;" :: "r"(dst), "l"(src));
}
#define CPA_COMMIT() asm volatile("cp.async.commit_group;" ::: "memory")
#define CPA_WAIT(n)  asm volatile("cp.async.wait_group %0;" :: "n"(n) : "memory")

// ---------------- weight prep (streaming, 2x float4/thread) ----------------
__global__ void cvt_h_kernel(const float* __restrict__ in, __half* __restrict__ out, size_t n4) {
    size_t half4 = n4 >> 1;
    size_t i = (size_t)blockIdx.x * 256 + threadIdx.x;
    if (i >= half4) return;
    __half2* o = (__half2*)out;
#pragma unroll
    for (int r = 0; r < 2; r++) {
        size_t idx = i + r * half4;
        float4 v = __ldcs((const float4*)in + idx);
        __stcs(o + idx * 2, __floats2half2_rn(v.x, v.y));
        __stcs(o + idx * 2 + 1, __floats2half2_rn(v.z, v.w));
    }
}

// ---------------- cp.async 3-stage fp16 GEMM ----------------
// LOSS: no C write; per-row (max,sumexp) partials + target logit capture.
// ACCF16: accumulate each BK-chunk in fp16 (2x HMMA rate if HW supports), spill to fp32.
template<int TH, int BM, int BN, int WR, int WC, bool BNK, bool BIAS, bool RELU,
         bool ACCUM, bool OUTH, bool GATHER, bool LOSS, bool ACCF16>
__global__ void __launch_bounds__(TH)
hgemm_ca(const __half* __restrict__ A, const __half* __restrict__ B,
         const float* __restrict__ bias, void* __restrict__ Cv,
         const int* __restrict__ gsel,
         const int* __restrict__ lids, float2* __restrict__ part,
         float* __restrict__ tlog,
         int K, int lda, int ldb, int ldc, int zdiv,
         size_t sA, size_t sA2, size_t sB, size_t sB2,
         size_t sC, size_t sC2, size_t sBias, float scale)
{
    constexpr int BK = 64;
    constexpr int LDS = 72;
    constexpr int BNP = BN + 8;
    constexpr int WM = BM / WR, WN = BN / WC;
    constexpr int MT = WM / 16, NT4 = WN / 8, NP = NT4 / 2;
    constexpr int ANV = (BM * 8) / TH;
    constexpr int BNV = BNK ? (BN * 8) / TH : (BK * BN) / (8 * TH);
    constexpr int STG = BNK ? (BM + BN) * LDS : BM * LDS + BK * BNP;

    const int m0 = blockIdx.y * BM, n0 = blockIdx.x * BN;
    const int tid = threadIdx.x, lane = tid & 31, warp = tid >> 5;
    const int wr = warp / WC, wc = warp % WC;
    const int g = lane >> 2, t = lane & 3;

    {
        int z = blockIdx.z, z1 = z / zdiv, z0 = z - z1 * zdiv;
        A += (size_t)z1 * sA + (size_t)z0 * sA2;
        B += (size_t)z1 * sB + (size_t)z0 * sB2;
        Cv = (char*)Cv + ((size_t)z1 * sC + (size_t)z0 * sC2) * (OUTH ? 2 : 4);
        if (BIAS) bias += (size_t)z1 * sBias;
    }

    const int nk = K / BK;

    extern __shared__ __half shh[];
    const uint32_t sbase = smem_u32(shh);

    const int a_r = lane & 15, a_c8 = (lane >> 4) * 8;
    const int b_r = (lane & 7) + (lane >> 4) * 8, b_c8 = ((lane >> 3) & 1) * 8;
    const int q8 = lane & 7, quad = lane >> 3;
    const int bt_k = (quad & 1) * 8 + q8, bt_n8 = (quad >> 1) * 8;
    const int mwb = wr * WM, nwb = wc * WN;

    const int ar = tid >> 3, aq = tid & 7;
    int arows[ANV];
#pragma unroll
    for (int i = 0; i < ANV; i++) {
        int r = m0 + ar + i * (TH >> 3);
        arows[i] = GATHER ? gsel[(size_t)blockIdx.z * NCAP + r] : r;
    }

    auto issue = [&](int ks, int st) {
        uint32_t so = sbase + (uint32_t)(st * STG) * 2;
#pragma unroll
        for (int i = 0; i < ANV; i++) {
            int row = ar + i * (TH >> 3);
            cpa16(so + (uint32_t)(row * LDS + aq * 8) * 2,
                  A + (size_t)arows[i] * lda + ks * BK + aq * 8);
        }
        if (BNK) {
            const __half* Bc = B + (size_t)n0 * ldb + ks * BK;
#pragma unroll
            for (int i = 0; i < BNV; i++) {
                int row = ar + i * (TH >> 3);
                cpa16(so + (uint32_t)((BM + row) * LDS + aq * 8) * 2,
                      Bc + (size_t)row * ldb + aq * 8);
            }
        } else {
            const __half* Bc = B + (size_t)(ks * BK) * ldb + n0;
#pragma unroll
            for (int i = 0; i < BNV; i++) {
                int idx = tid + i * TH;
                int kk = idx / (BN / 8), nq = idx % (BN / 8);
                cpa16(so + (uint32_t)(BM * LDS + kk * BNP + nq * 8) * 2,
                      Bc + (size_t)kk * ldb + nq * 8);
            }
        }
        CPA_COMMIT();
    };

    float acc[MT][NT4][4] = {};

    issue(0, 0);
    if (nk > 1) issue(1, 1);
    if (nk > 1) { CPA_WAIT(1); } else { CPA_WAIT(0); }
    __syncthreads();

    for (int ks = 0; ks < nk; ks++) {
        int cur = ks % 3;
        bool more2 = (ks + 2 < nk);
        if (more2) issue(ks + 2, (ks + 2) % 3);
        uint32_t abase = sbase + (uint32_t)(cur * STG) * 2;
        uint32_t bbase = abase + (uint32_t)(BM * LDS) * 2;
        unsigned hacc[ACCF16 ? MT : 1][ACCF16 ? NT4 : 1][2];
        if (ACCF16) {
#pragma unroll
            for (int mt = 0; mt < MT; mt++)
#pragma unroll
                for (int nt = 0; nt < NT4; nt++) { hacc[mt][nt][0] = 0u; hacc[mt][nt][1] = 0u; }
        }
#pragma unroll
        for (int kq = 0; kq < 4; kq++) {
            unsigned af[MT][4], bf[NT4][2];
#pragma unroll
            for (int mt = 0; mt < MT; mt++) {
                uint32_t ad = abase +
                    (uint32_t)(((mwb + mt * 16 + a_r) * LDS + kq * 16 + a_c8) * 2);
                ldsm4(af[mt][0], af[mt][1], af[mt][2], af[mt][3], ad);
            }
            if (BNK) {
#pragma unroll
                for (int np = 0; np < NP; np++) {
                    uint32_t bd = bbase +
                        (uint32_t)(((nwb + np * 16 + b_r) * LDS + kq * 16 + b_c8) * 2);
                    ldsm4(bf[2*np][0], bf[2*np][1], bf[2*np+1][0], bf[2*np+1][1], bd);
                }
            } else {
#pragma unroll
                for (int np = 0; np < NP; np++) {
                    uint32_t bd = bbase +
                        (uint32_t)(((kq * 16 + bt_k) * BNP + nwb + np * 16 + bt_n8) * 2);
                    ldsm4t(bf[2*np][0], bf[2*np][1], bf[2*np+1][0], bf[2*np+1][1], bd);
                }
            }
#pragma unroll
            for (int mt = 0; mt < MT; mt++)
#pragma unroll
                for (int nt = 0; nt < NT4; nt++) {
                    if (ACCF16) mma_f16h(hacc[mt][nt], af[mt], bf[nt]);
                    else        mma_f16(acc[mt][nt], af[mt], bf[nt]);
                }
        }
        if (ACCF16) {
#pragma unroll
            for (int mt = 0; mt < MT; mt++)
#pragma unroll
                for (int nt = 0; nt < NT4; nt++) {
                    float2 lo = __half22float2(*(__half2*)&hacc[mt][nt][0]);
                    float2 hi = __half22float2(*(__half2*)&hacc[mt][nt][1]);
                    acc[mt][nt][0] += lo.x; acc[mt][nt][1] += lo.y;
                    acc[mt][nt][2] += hi.x; acc[mt][nt][3] += hi.y;
                }
        }
        if (ks + 1 < nk) {
            if (more2) { CPA_WAIT(1); } else { CPA_WAIT(0); }
            __syncthreads();
        }
    }

    if (LOSS) {
        __syncthreads();
        float2* psh = (float2*)shh;           // [BM][WC]
#pragma unroll
        for (int mt = 0; mt < MT; mt++) {
            int rl = mwb + mt * 16 + g, rh = rl + 8;
            float ml = -1e30f, mh = -1e30f;
#pragma unroll
            for (int nt = 0; nt < NT4; nt++) {
                ml = fmaxf(ml, fmaxf(acc[mt][nt][0], acc[mt][nt][1]));
                mh = fmaxf(mh, fmaxf(acc[mt][nt][2], acc[mt][nt][3]));
            }
            ml = fmaxf(ml, __shfl_xor_sync(~0u, ml, 1));
            ml = fmaxf(ml, __shfl_xor_sync(~0u, ml, 2));
            mh = fmaxf(mh, __shfl_xor_sync(~0u, mh, 1));
            mh = fmaxf(mh, __shfl_xor_sync(~0u, mh, 2));
            float sl = 0.f, shi = 0.f;
#pragma unroll
            for (int nt = 0; nt < NT4; nt++) {
                sl += __expf(acc[mt][nt][0] - ml) + __expf(acc[mt][nt][1] - ml);
                shi += __expf(acc[mt][nt][2] - mh) + __expf(acc[mt][nt][3] - mh);
            }
            sl += __shfl_xor_sync(~0u, sl, 1);
            sl += __shfl_xor_sync(~0u, sl, 2);
            shi += __shfl_xor_sync(~0u, shi, 1);
            shi += __shfl_xor_sync(~0u, shi, 2);
            if (t == 0) {
                psh[rl * WC + wc] = make_float2(ml, sl);
                psh[rh * WC + wc] = make_float2(mh, shi);
            }
            int grl = m0 + rl, grh = m0 + rh;
            int tgl = ((grl % NT) != NT - 1) ? lids[grl + 1] : -1;
            int tgh = ((grh % NT) != NT - 1) ? lids[grh + 1] : -1;
#pragma unroll
            for (int nt = 0; nt < NT4; nt++) {
                int c0 = n0 + nwb + nt * 8 + 2 * t;
                if (c0 == tgl)     tlog[grl] = acc[mt][nt][0];
                if (c0 + 1 == tgl) tlog[grl] = acc[mt][nt][1];
                if (c0 == tgh)     tlog[grh] = acc[mt][nt][2];
                if (c0 + 1 == tgh) tlog[grh] = acc[mt][nt][3];
            }
        }
        __syncthreads();
        if (tid < BM) {
            float m = -1e30f, s = 0.f;
#pragma unroll
            for (int w = 0; w < WC; w++) {
                float2 p = psh[tid * WC + w];
                if (p.x > m) { s = s * __expf(m - p.x) + p.y; m = p.x; }
                else s += p.y * __expf(p.x - m);
            }
            part[(size_t)(m0 + tid) * NPART + blockIdx.x] = make_float2(m, s);
        }
        return;
    }

    __half* Ch = (__half*)Cv;
    float*  Cf = (float*)Cv;
#pragma unroll
    for (int mt = 0; mt < MT; mt++) {
#pragma unroll
        for (int nt = 0; nt < NT4; nt++) {
            int r0 = m0 + mwb + mt * 16 + g;
            int c0 = n0 + nwb + nt * 8 + 2 * t;
            float v0 = acc[mt][nt][0] * scale, v1 = acc[mt][nt][1] * scale;
            float v2 = acc[mt][nt][2] * scale, v3 = acc[mt][nt][3] * scale;
            if (BIAS) {
                float b0 = bias[c0], b1 = bias[c0 + 1];
                v0 += b0; v1 += b1; v2 += b0; v3 += b1;
            }
            if (RELU) {
                v0 = fmaxf(v0, 0.f); v1 = fmaxf(v1, 0.f);
                v2 = fmaxf(v2, 0.f); v3 = fmaxf(v3, 0.f);
            }
            if (OUTH) {
                *(__half2*)(Ch + (size_t)r0 * ldc + c0) = __floats2half2_rn(v0, v1);
                *(__half2*)(Ch + (size_t)(r0 + 8) * ldc + c0) = __floats2half2_rn(v2, v3);
            } else {
                float* p0 = Cf + (size_t)r0 * ldc + c0;
                float* p1 = Cf + (size_t)(r0 + 8) * ldc + c0;
                if (ACCUM) {
                    float2 o0 = *(float2*)p0, o1 = *(float2*)p1;
                    v0 += o0.x; v1 += o0.y; v2 += o1.x; v3 += o1.y;
                }
                *(float2*)p0 = make_float2(v0, v1);
                *(float2*)p1 = make_float2(v2, v3);
            }
        }
    }
}

// ---------------- FlashAttention-2 (causal, 128-row q-tiles, 256 thr) ----------------
#define FL_PITCH 72
#define FL_QSZ   (128 * FL_PITCH)
#define FL_KVSZ  (2 * 128 * FL_PITCH)
#define FL_SMEM  ((FL_QSZ + 2 * FL_KVSZ) * 2)

__global__ void __launch_bounds__(256)
flash_kernel(const __half* __restrict__ qkv, __half* __restrict__ attn) {
    int z = blockIdx.y, b = z >> 4, h = z & 15;
    int qt = (int)gridDim.x - 1 - (int)blockIdx.x;
    int m0 = qt * 128;
    const __half* Qg = qkv + (size_t)b * NT * 3072 + h * 64;
    const __half* Kg = Qg + 1024;
    const __half* Vg = Qg + 2048;

    extern __shared__ __half sh[];
    const uint32_t sb = smem_u32(sh);

    int tid = threadIdx.x, lane = tid & 31, warp = tid >> 5;
    int g = lane >> 2, t = lane & 3;
    int lr = tid >> 3, lq = tid & 7;

#pragma unroll
    for (int i = 0; i < 4; i++) {
        int row = lr + i * 32;
        cpa16(sb + (uint32_t)(row * FL_PITCH + lq * 8) * 2,
              Qg + (size_t)(m0 + row) * 3072 + lq * 8);
    }
    CPA_COMMIT();

    auto issue_kv = [&](int j, int st) {
        uint32_t so = sb + (uint32_t)(FL_QSZ + st * FL_KVSZ) * 2;
#pragma unroll
        for (int i = 0; i < 4; i++) {
            int row = lr + i * 32;
            cpa16(so + (uint32_t)(row * FL_PITCH + lq * 8) * 2,
                  Kg + (size_t)(j * 128 + row) * 3072 + lq * 8);
        }
#pragma unroll
        for (int i = 0; i < 4; i++) {
            int row = lr + i * 32;
            cpa16(so + (uint32_t)((128 + row) * FL_PITCH + lq * 8) * 2,
                  Vg + (size_t)(j * 128 + row) * 3072 + lq * 8);
        }
        CPA_COMMIT();
    };
    issue_kv(0, 0);
    CPA_WAIT(0);
    __syncthreads();

    const int mwb = warp * 16;
    const int a_r = lane & 15, a_c8 = (lane >> 4) * 8;
    unsigned qf[4][4];
#pragma unroll
    for (int kq = 0; kq < 4; kq++) {
        uint32_t ad = sb + (uint32_t)(((mwb + a_r) * FL_PITCH + kq * 16 + a_c8) * 2);
        ldsm4(qf[kq][0], qf[kq][1], qf[kq][2], qf[kq][3], ad);
    }

    const int b_r = (lane & 7) + (lane >> 4) * 8, b_c8 = ((lane >> 3) & 1) * 8;
    const int q8 = lane & 7, quad = lane >> 3;
    const int bt_k = (quad & 1) * 8 + q8, bt_n8 = (quad >> 1) * 8;

    float m_lo = -1e30f, m_hi = -1e30f, l_lo = 0.f, l_hi = 0.f;
    float ao[8][4] = {};
    const int rl_lo = mwb + g, rl_hi = mwb + g + 8;

    for (int j = 0; j <= qt; j++) {
        int st = j & 1;
        __syncthreads();
        if (j < qt) issue_kv(j + 1, st ^ 1);
        if (j < qt) { CPA_WAIT(1); } else { CPA_WAIT(0); }
        __syncthreads();

        uint32_t kbase = sb + (uint32_t)(FL_QSZ + st * FL_KVSZ) * 2;
        uint32_t vbase = kbase + (uint32_t)(128 * FL_PITCH) * 2;

        float as[16][4] = {};
#pragma unroll
        for (int kq = 0; kq < 4; kq++) {
            unsigned bf[16][2];
#pragma unroll
            for (int np = 0; np < 8; np++) {
                uint32_t bd = kbase +
                    (uint32_t)(((np * 16 + b_r) * FL_PITCH + kq * 16 + b_c8) * 2);
                ldsm4(bf[2*np][0], bf[2*np][1], bf[2*np+1][0], bf[2*np+1][1], bd);
            }
#pragma unroll
            for (int nt = 0; nt < 16; nt++)
                mma_f16(as[nt], qf[kq], bf[nt]);
        }

        float rm_lo = -1e30f, rm_hi = -1e30f;
#pragma unroll
        for (int nt = 0; nt < 16; nt++) {
            int c0 = nt * 8 + 2 * t;
            as[nt][0] *= 0.125f; as[nt][1] *= 0.125f;
            as[nt][2] *= 0.125f; as[nt][3] *= 0.125f;
            if (j == qt) {
                if (c0     > rl_lo) as[nt][0] = -1e30f;
                if (c0 + 1 > rl_lo) as[nt][1] = -1e30f;
                if (c0     > rl_hi) as[nt][2] = -1e30f;
                if (c0 + 1 > rl_hi) as[nt][3] = -1e30f;
            }
            rm_lo = fmaxf(rm_lo, fmaxf(as[nt][0], as[nt][1]));
            rm_hi = fmaxf(rm_hi, fmaxf(as[nt][2], as[nt][3]));
        }
        rm_lo = fmaxf(rm_lo, __shfl_xor_sync(~0u, rm_lo, 1));
        rm_lo = fmaxf(rm_lo, __shfl_xor_sync(~0u, rm_lo, 2));
        rm_hi = fmaxf(rm_hi, __shfl_xor_sync(~0u, rm_hi, 1));
        rm_hi = fmaxf(rm_hi, __shfl_xor_sync(~0u, rm_hi, 2));
        float mn_lo = fmaxf(m_lo, rm_lo), mn_hi = fmaxf(m_hi, rm_hi);
        float sf_lo = __expf(m_lo - mn_lo), sf_hi = __expf(m_hi - mn_hi);
        m_lo = mn_lo; m_hi = mn_hi;

        float rs_lo = 0.f, rs_hi = 0.f;
        unsigned pf[16][2];
#pragma unroll
        for (int nt = 0; nt < 16; nt++) {
            float p0 = __expf(as[nt][0] - mn_lo), p1 = __expf(as[nt][1] - mn_lo);
            float p2 = __expf(as[nt][2] - mn_hi), p3 = __expf(as[nt][3] - mn_hi);
            rs_lo += p0 + p1; rs_hi += p2 + p3;
            __half2 h01 = __floats2half2_rn(p0, p1);
            __half2 h23 = __floats2half2_rn(p2, p3);
            pf[nt][0] = *(unsigned*)&h01;
            pf[nt][1] = *(unsigned*)&h23;
        }
        rs_lo += __shfl_xor_sync(~0u, rs_lo, 1);
        rs_lo += __shfl_xor_sync(~0u, rs_lo, 2);
        rs_hi += __shfl_xor_sync(~0u, rs_hi, 1);
        rs_hi += __shfl_xor_sync(~0u, rs_hi, 2);
        l_lo = l_lo * sf_lo + rs_lo;
        l_hi = l_hi * sf_hi + rs_hi;
#pragma unroll
        for (int nt = 0; nt < 8; nt++) {
            ao[nt][0] *= sf_lo; ao[nt][1] *= sf_lo;
            ao[nt][2] *= sf_hi; ao[nt][3] *= sf_hi;
        }
#pragma unroll
        for (int kc = 0; kc < 8; kc++) {
            unsigned af[4] = { pf[2*kc][0], pf[2*kc][1], pf[2*kc+1][0], pf[2*kc+1][1] };
            unsigned vf[8][2];
#pragma unroll
            for (int np = 0; np < 4; np++) {
                uint32_t bd = vbase +
                    (uint32_t)(((kc * 16 + bt_k) * FL_PITCH + np * 16 + bt_n8) * 2);
                ldsm4t(vf[2*np][0], vf[2*np][1], vf[2*np+1][0], vf[2*np+1][1], bd);
            }
#pragma unroll
            for (int nt = 0; nt < 8; nt++)
                mma_f16(ao[nt], af, vf[nt]);
        }
    }

    float il_lo = 1.f / l_lo, il_hi = 1.f / l_hi;
    __half* Ob = attn + (size_t)(b * NT + m0) * ND + h * 64;
#pragma unroll
    for (int nt = 0; nt < 8; nt++) {
        int c0 = nt * 8 + 2 * t;
        *(__half2*)(Ob + (size_t)(mwb + g) * ND + c0) =
            __floats2half2_rn(ao[nt][0] * il_lo, ao[nt][1] * il_lo);
        *(__half2*)(Ob + (size_t)(mwb + g + 8) * ND + c0) =
            __floats2half2_rn(ao[nt][2] * il_hi, ao[nt][3] * il_hi);
    }
}

// ---------------- small kernels ----------------
__global__ void embed_kernel(const int* __restrict__ ids, const float* __restrict__ tok,
                             const float* __restrict__ pos, float* __restrict__ x) {
    int n = blockIdx.x, t = n % NT, id = ids[n];
    const float* te = tok + (size_t)id * ND;
    const float* pe = pos + (size_t)t * ND;
    float* dst = x + (size_t)n * ND;
    for (int d = threadIdx.x; d < ND; d += 256) dst[d] = te[d] + pe[d];
}

__global__ void ln_kernel(const float* __restrict__ x, const float* __restrict__ w,
                          const float* __restrict__ b, __half* __restrict__ out) {
    int row = blockIdx.x * 8 + (threadIdx.x >> 5);
    int lane = threadIdx.x & 31;
    const float4* p = (const float4*)(x + (size_t)row * ND);
    float4 v[8];
    float s = 0.f;
#pragma unroll
    for (int i = 0; i < 8; i++) {
        v[i] = p[lane + i * 32];
        s += v[i].x + v[i].y + v[i].z + v[i].w;
    }
#pragma unroll
    for (int o = 16; o; o >>= 1) s += __shfl_xor_sync(~0u, s, o);
    float mu = s * (1.0f / ND);
    float q = 0.f;
#pragma unroll
    for (int i = 0; i < 8; i++) {
        float a = v[i].x - mu, c = v[i].y - mu, d = v[i].z - mu, e = v[i].w - mu;
        q += a * a + c * c + d * d + e * e;
    }
#pragma unroll
    for (int o = 16; o; o >>= 1) q += __shfl_xor_sync(~0u, q, o);
    float rs = rsqrtf(q * (1.0f / ND) + 1e-5f);
    const float4* wp = (const float4*)w;
    const float4* bp = (const float4*)b;
    __half2* op = (__half2*)(out + (size_t)row * ND);
#pragma unroll
    for (int i = 0; i < 8; i++) {
        int j = lane + i * 32;
        float4 wv = wp[j], bv = bp[j];
        op[j * 2] = __floats2half2_rn((v[i].x - mu) * rs * wv.x + bv.x,
                                      (v[i].y - mu) * rs * wv.y + bv.y);
        op[j * 2 + 1] = __floats2half2_rn((v[i].z - mu) * rs * wv.z + bv.z,
                                          (v[i].w - mu) * rs * wv.w + bv.w);
    }
}

__global__ void rope_kernel(__half* __restrict__ qkv) {
    int n = blockIdx.x, t = n % NT;
    __half* base = qkv + (size_t)n * 3072;
#pragma unroll
    for (int item = threadIdx.x; item < 512; item += 256) {
        int h = item >> 5, i = item & 31;
        float ang = (float)t * expf((float)(2 * i) * (-0.14391156831212806f));
        float s = sinf(ang), c = cosf(ang);
        __half* q = base + h * 64;
        __half* k = q + 1024;
        float q1 = __half2float(q[i]), q2 = __half2float(q[i + 32]);
        q[i] = __float2half_rn(q1 * c - q2 * s);
        q[i + 32] = __float2half_rn(q2 * c + q1 * s);
        float k1 = __half2float(k[i]), k2 = __half2float(k[i + 32]);
        k[i] = __float2half_rn(k1 * c - k2 * s);
        k[i + 32] = __float2half_rn(k2 * c + k1 * s);
    }
}

// ---------------- MoE ----------------
__global__ void route_kernel(const __half* __restrict__ ln, const float* __restrict__ wr,
                             const float* __restrict__ br, const float* __restrict__ wn,
                             const float* __restrict__ bn, float* __restrict__ route,
                             float* __restrict__ noise) {
    int n = blockIdx.x, tid = threadIdx.x;
    __shared__ float xs[ND];
    for (int d = tid; d < ND; d += 256) xs[d] = __half2float(ln[(size_t)n * ND + d]);
    __syncthreads();
    int w = tid >> 5, lane = tid & 31;
    float sr = 0.f, sn = 0.f;
    for (int d = lane; d < ND; d += 32) {
        float xv = xs[d];
        sr += xv * wr[(size_t)d * NE + w];
        sn += xv * wn[(size_t)d * NE + w];
    }
    for (int o = 16; o; o >>= 1) { sr += __shfl_down_sync(~0u, sr, o); sn += __shfl_down_sync(~0u, sn, o); }
    if (!lane) { route[n * NE + w] = sr + br[w]; noise[n * NE + w] = sn + bn[w]; }
}

__global__ void topk_kernel(const float* __restrict__ route, const float* __restrict__ noise,
                            unsigned k0, unsigned k1, float* __restrict__ gate,
                            unsigned char* __restrict__ mask) {
    int n = blockIdx.x * 256 + threadIdx.x;
    if (n >= NN) return;
    float nv[NE];
#pragma unroll
    for (int e = 0; e < NE; e++) {
        unsigned o0, o1;
        threefry(k0, k1, 0u, (unsigned)(n * NE + e), o0, o1);
        float ep = bits_to_normal(o0 ^ o1);
        float x = noise[n * NE + e];
        float sp = fmaxf(x, 0.f) + log1pf(expf(-fabsf(x)));
        nv[e] = route[n * NE + e] + ep * sp;
    }
    int i1 = 0; float v1 = nv[0];
#pragma unroll
    for (int e = 1; e < NE; e++) if (nv[e] > v1) { v1 = nv[e]; i1 = e; }
    int i2 = -1; float v2 = -3.4e38f;
#pragma unroll
    for (int e = 0; e < NE; e++) if (e != i1 && nv[e] > v2) { v2 = nv[e]; i2 = e; }
    float e2 = expf(v2 - v1);
    float Z = 1.0f + e2;
#pragma unroll
    for (int e = 0; e < NE; e++)
        gate[n * NE + e] = (e == i1) ? (1.0f / Z) : ((e == i2) ? (e2 / Z) : 0.f);
    mask[n] = (unsigned char)((1u << i1) | (1u << i2));
}

__global__ void select_kernel(const unsigned char* __restrict__ mask, int* __restrict__ sel,
                              int* __restrict__ slot, int* __restrict__ cnt) {
    int e = blockIdx.x, lane = threadIdx.x;
    int base = 0;
    for (int n0 = 0; n0 < NN; n0 += 32) {
        int n = n0 + lane;
        bool f = (mask[n] >> e) & 1;
        unsigned bal = __ballot_sync(0xffffffffu, f);
        int pos = base + __popc(bal & ((1u << lane) - 1u));
        int sl = (f && pos < NCAP) ? pos : -1;
        slot[(size_t)e * NN + n] = sl;
        if (sl >= 0) sel[e * NCAP + sl] = n;
        base += __popc(bal);
    }
    if (!lane) cnt[e] = base < NCAP ? base : NCAP;
}

// fused scatter + next LayerNorm
__global__ void moe_scatter_ln_kernel(const __half* __restrict__ eo, const int* __restrict__ slot,
                                      const float* __restrict__ gate, float* __restrict__ x,
                                      const float* __restrict__ w, const float* __restrict__ b,
                                      __half* __restrict__ lnout) {
    int n = blockIdx.x, tid = threadIdx.x;
    __shared__ int ss[NE];
    __shared__ float gg[NE];
    __shared__ float red[8];
    if (tid < NE) { ss[tid] = slot[(size_t)tid * NN + n]; gg[tid] = gate[n * NE + tid]; }
    __syncthreads();
    float vals[4];
    float s = 0.f;
#pragma unroll
    for (int i = 0; i < 4; i++) {
        int d = tid + i * 256;
        float acc = x[(size_t)n * ND + d];
#pragma unroll
        for (int e = 0; e < NE; e++) {
            int sl = ss[e];
            if (sl >= 0) acc += gg[e] * __half2float(eo[((size_t)e * NCAP + sl) * ND + d]);
        }
        vals[i] = acc; s += acc;
        x[(size_t)n * ND + d] = acc;
    }
    int lane = tid & 31, warp = tid >> 5;
#pragma unroll
    for (int o = 16; o; o >>= 1) s += __shfl_xor_sync(~0u, s, o);
    if (!lane) red[warp] = s;
    __syncthreads();
    if (tid < 8) {
        float t = red[tid];
#pragma unroll
        for (int o = 4; o; o >>= 1) t += __shfl_xor_sync(0xffu, t, o);
        red[tid] = t;
    }
    __syncthreads();
    float mu = red[0] * (1.0f / ND);
    float q = 0.f;
#pragma unroll
    for (int i = 0; i < 4; i++) { float d = vals[i] - mu; q += d * d; }
#pragma unroll
    for (int o = 16; o; o >>= 1) q += __shfl_xor_sync(~0u, q, o);
    __syncthreads();
    if (!lane) red[warp] = q;
    __syncthreads();
    if (tid < 8) {
        float t = red[tid];
#pragma unroll
        for (int o = 4; o; o >>= 1) t += __shfl_xor_sync(0xffu, t, o);
        red[tid] = t;
    }
    __syncthreads();
    float rs = rsqrtf(red[0] * (1.0f / ND) + 1e-5f);
#pragma unroll
    for (int i = 0; i < 4; i++) {
        int d = tid + i * 256;
        lnout[(size_t)n * ND + d] =
            __float2half_rn((vals[i] - mu) * rs * w[d] + b[d]);
    }
}

// ---------------- loss final ----------------
__global__ void loss_final_kernel(const float2* __restrict__ part, const float* __restrict__ tlog,
                                  const int* __restrict__ ids, float* __restrict__ nll,
                                  float* __restrict__ vld) {
    int n = blockIdx.x, lane = threadIdx.x;
    int t = n % NT;
    if (t == NT - 1) { if (!lane) { nll[n] = 0.f; vld[n] = 0.f; } return; }
    float m = -1e30f, s = 0.f;
    for (int j = lane; j < NPART; j += 32) {
        float2 p = part[(size_t)n * NPART + j];
        if (p.x > m) { s = s * __expf(m - p.x) + p.y; m = p.x; }
        else s += p.y * __expf(p.x - m);
    }
#pragma unroll
    for (int o = 16; o; o >>= 1) {
        float m2 = __shfl_xor_sync(~0u, m, o);
        float s2 = __shfl_xor_sync(~0u, s, o);
        float M = fmaxf(m, m2);
        s = s * __expf(m - M) + s2 * __expf(m2 - M);
        m = M;
    }
    if (!lane) {
        float lse = m + logf(s);
        int tgt = ids[n + 1];
        float v = (tgt != 2) ? 1.f : 0.f;
        nll[n] = -(tlog[n] - lse) * v;
        vld[n] = v;
    }
}

__global__ void reduce_kernel(const float* __restrict__ nll, const float* __restrict__ vld,
                              float* __restrict__ out) {
    __shared__ float s1[256], s2[256];
    int tid = threadIdx.x;
    float a = 0.f, b = 0.f;
    for (int i = tid; i < NN; i += 256) { a += nll[i]; b += vld[i]; }
    s1[tid] = a; s2[tid] = b; __syncthreads();
    for (int st = 128; st; st >>= 1) { if (tid < st) { s1[tid] += s1[tid + st]; s2[tid] += s2[tid + st]; } __syncthreads(); }
    if (!tid) out[0] = s1[0] / fmaxf(s2[0], 1.0f);
}

// ---------------- host launch ----------------
#define STG_T(BM, BN) (((BM) + (BN)) * 72)
#define STG_F(BM, BN) ((BM) * 72 + 64 * ((BN) + 8))

extern "C" void kernel_launch(void* const* d_in, const int* in_sizes, int n_in,
                              void* d_out, int out_size) {
    const int*   ids     = (const int*)d_in[0];
    const float* tok_emb = (const float*)d_in[1];
    const float* pos_emb = (const float*)d_in[2];
    const float* ln1_w   = (const float*)d_in[3];
    const float* ln1_b   = (const float*)d_in[4];
    const float* ln2_w   = (const float*)d_in[5];
    const float* ln2_b   = (const float*)d_in[6];
    const float* w_qkv   = (const float*)d_in[7];
    const float* w_out   = (const float*)d_in[8];
    const float* w_route = (const float*)d_in[9];
    const float* b_route = (const float*)d_in[10];
    const float* w_noise = (const float*)d_in[11];
    const float* b_noise = (const float*)d_in[12];
    const float* w_e1    = (const float*)d_in[13];
    const float* b_e1    = (const float*)d_in[14];
    const float* w_e2    = (const float*)d_in[15];
    const float* b_e2    = (const float*)d_in[16];
    const float* lnf_w   = (const float*)d_in[17];
    const float* lnf_b   = (const float*)d_in[18];
    float* out = (float*)d_out;

    float *x, *route, *noise, *gate, *nll, *vld, *tlog;
    float2* part;
    __half *ln16, *qkv16, *attn16, *h116, *eo16;
    __half *wqkv16, *wout16, *we116, *we216, *tok16;
    unsigned char* mask; int *sel, *slot, *cnt;
    cudaGetSymbolAddress((void**)&x, g_x);
    cudaGetSymbolAddress((void**)&ln16, g_ln16);
    cudaGetSymbolAddress((void**)&qkv16, g_qkv16);
    cudaGetSymbolAddress((void**)&attn16, g_attn16);
    cudaGetSymbolAddress((void**)&route, g_route);
    cudaGetSymbolAddress((void**)&noise, g_noise);
    cudaGetSymbolAddress((void**)&gate, g_gate);
    cudaGetSymbolAddress((void**)&mask, g_mask);
    cudaGetSymbolAddress((void**)&sel, g_sel);
    cudaGetSymbolAddress((void**)&slot, g_slot);
    cudaGetSymbolAddress((void**)&cnt, g_cnt);
    cudaGetSymbolAddress((void**)&h116, g_h116);
    cudaGetSymbolAddress((void**)&eo16, g_eo16);
    cudaGetSymbolAddress((void**)&part, g_part);
    cudaGetSymbolAddress((void**)&tlog, g_tlog);
    cudaGetSymbolAddress((void**)&nll, g_nll);
    cudaGetSymbolAddress((void**)&vld, g_vld);
    cudaGetSymbolAddress((void**)&wqkv16, g_wqkv16);
    cudaGetSymbolAddress((void**)&wout16, g_wout16);
    cudaGetSymbolAddress((void**)&we116, g_we116);
    cudaGetSymbolAddress((void**)&we216, g_we216);
    cudaGetSymbolAddress((void**)&tok16, g_tok16);

    constexpr int SM_T = 3 * STG_T(256, 128) * 2;
    constexpr int SM_F = 3 * STG_F(256, 128) * 2;
    auto* kqkv = hgemm_ca<512,256,128,4,4,false,false,false,false,true ,false,false,false>;
    auto* kproj= hgemm_ca<512,256,128,4,4,false,false,false,true ,false,false,false,false>;
    auto* kfc1 = hgemm_ca<512,256,128,4,4,false,true ,true ,false,true ,true ,false,false>;
    auto* kfc2 = hgemm_ca<512,256,128,4,4,false,true ,false,false,true ,false,false,false>;
    auto* kvoc = hgemm_ca<512,256,128,4,4,true ,false,false,false,false,false,true ,true >;
    cudaFuncSetAttribute(kqkv, cudaFuncAttributeMaxDynamicSharedMemorySize, SM_F);
    cudaFuncSetAttribute(kproj,cudaFuncAttributeMaxDynamicSharedMemorySize, SM_F);
    cudaFuncSetAttribute(kfc1, cudaFuncAttributeMaxDynamicSharedMemorySize, SM_F);
    cudaFuncSetAttribute(kfc2, cudaFuncAttributeMaxDynamicSharedMemorySize, SM_F);
    cudaFuncSetAttribute(kvoc, cudaFuncAttributeMaxDynamicSharedMemorySize, SM_T);
    cudaFuncSetAttribute(flash_kernel, cudaFuncAttributeMaxDynamicSharedMemorySize, FL_SMEM);

    static cudaStream_t s1 = [] { cudaStream_t s; cudaStreamCreateWithFlags(&s, cudaStreamNonBlocking); return s; }();
    static cudaEvent_t evF = [] { cudaEvent_t e; cudaEventCreateWithFlags(&e, cudaEventDisableTiming); return e; }();
    static cudaEvent_t evJ = [] { cudaEvent_t e; cudaEventCreateWithFlags(&e, cudaEventDisableTiming); return e; }();

    cudaEventRecord(evF, 0);
    cudaStreamWaitEvent(s1, evF, 0);
    {
        size_t n;
        n = (size_t)NLAY * NE * ND * NFF / 4;
        cvt_h_kernel<<<(unsigned)((n / 2 + 255) / 256), 256, 0, s1>>>(w_e1, we116, n);
        n = (size_t)NLAY * NE * NFF * ND / 4;
        cvt_h_kernel<<<(unsigned)((n / 2 + 255) / 256), 256, 0, s1>>>(w_e2, we216, n);
        n = (size_t)NV * ND / 4;
        cvt_h_kernel<<<(unsigned)((n / 2 + 255) / 256), 256, 0, s1>>>(tok_emb, tok16, n);
    }
    cudaEventRecord(evJ, s1);

    {
        size_t n;
        n = (size_t)NLAY * ND * 3 * ND / 4;
        cvt_h_kernel<<<(unsigned)((n / 2 + 255) / 256), 256>>>(w_qkv, wqkv16, n);
        n = (size_t)NLAY * ND * ND / 4;
        cvt_h_kernel<<<(unsigned)((n / 2 + 255) / 256), 256>>>(w_out, wout16, n);
    }
    embed_kernel<<<NN, 256>>>(ids, tok_emb, pos_emb, x);
    ln_kernel<<<NN / 8, 256>>>(x, ln1_w, ln1_b, ln16);

    for (int l = 0; l < NLAY; l++) {
        // ---- attention ----
        kqkv<<<dim3(24, 16, 1), 512, SM_F>>>(
            ln16, wqkv16 + (size_t)l * ND * 3 * ND, nullptr, qkv16, nullptr,
            nullptr, nullptr, nullptr,
            ND, ND, 3 * ND, 3 * ND, 1, 0, 0, 0, 0, 0, 0, 0, 1.0f);
        rope_kernel<<<NN, 256>>>(qkv16);
        flash_kernel<<<dim3(NT / 128, NB * NH), 256, FL_SMEM>>>(qkv16, attn16);
        kproj<<<dim3(8, 16, 1), 512, SM_F>>>(
            attn16, wout16 + (size_t)l * ND * ND, nullptr, x, nullptr,
            nullptr, nullptr, nullptr,
            ND, ND, ND, ND, 1, 0, 0, 0, 0, 0, 0, 0, 1.0f);

        // ---- MoE ----
        ln_kernel<<<NN / 8, 256>>>(x, ln2_w + l * ND, ln2_b + l * ND, ln16);
        route_kernel<<<NN, 256>>>(ln16, w_route + (size_t)l * ND * NE, b_route + l * NE,
                                  w_noise + (size_t)l * ND * NE, b_noise + l * NE, route, noise);
        unsigned k0, k1;
        threefry(0u, 1234u, 0u, (unsigned)l, k0, k1);
        topk_kernel<<<(NN + 255) / 256, 256>>>(route, noise, k0, k1, gate, mask);
        select_kernel<<<NE, 32>>>(mask, sel, slot, cnt);
        if (l == 0) cudaStreamWaitEvent(0, evJ, 0);
        kfc1<<<dim3(32, 4, NE), 512, SM_F>>>(
            ln16, we116 + (size_t)l * NE * ND * NFF, b_e1 + (size_t)l * NE * NFF, h116, sel,
            nullptr, nullptr, nullptr,
            ND, ND, NFF, NFF, 1,
            0, 0, (size_t)NFF * ND, 0,
            (size_t)NCAP * NFF, 0, NFF, 1.0f);
        kfc2<<<dim3(8, 4, NE), 512, SM_F>>>(
            h116, we216 + (size_t)l * NE * NFF * ND, b_e2 + (size_t)l * NE * ND, eo16, nullptr,
            nullptr, nullptr, nullptr,
            NFF, NFF, ND, ND, 1,
            (size_t)NCAP * NFF, 0, (size_t)ND * NFF, 0,
            (size_t)NCAP * ND, 0, ND, 1.0f);
        const float* nw = (l + 1 < NLAY) ? (ln1_w + (size_t)(l + 1) * ND) : lnf_w;
        const float* nb = (l + 1 < NLAY) ? (ln1_b + (size_t)(l + 1) * ND) : lnf_b;
        moe_scatter_ln_kernel<<<NN, 256>>>(eo16, slot, gate, x, nw, nb, ln16);
    }

    // vocab GEMM with fused loss partials (fp16-accumulator experiment)
    kvoc<<<dim3(NPART, 16, 1), 512, SM_T>>>(
        ln16, tok16, nullptr, nullptr, nullptr,
        ids, part, tlog,
        ND, ND, ND, NV, 1, 0, 0, 0, 0, 0, 0, 0, 1.0f);
    loss_final_kernel<<<NN, 32>>>(part, tlog, ids, nll, vld);
    reduce_kernel<<<1, 256>>>(nll, vld, out);
}